// round 9
// baseline (speedup 1.0000x reference)
#include <cuda_runtime.h>
#include <cstdint>

#define BATCH 32
#define NSLOT 7
#define QDIM 64
#define HID 64
#define NPOS 16384

// ---- scratch (device globals; no allocation) ----
__device__ float g_bufA[(size_t)BATCH * HID * NPOS];
__device__ float g_bufB[(size_t)BATCH * HID * NPOS];
__device__ float g_keys[(size_t)BATCH * NPOS * QDIM];
__device__ float g_vals[(size_t)BATCH * NPOS * QDIM];
__device__ float g_Wt1[25 * 5 * HID];
__device__ float g_Wt2[25 * HID * HID];
__device__ float g_Wt3[25 * HID * HID];
__device__ float g_WkvT[HID * 128];
__device__ float g_WgruT[2 * 64 * 192];
__device__ float g_qbuf[BATCH * NSLOT * QDIM];
__device__ float g_qn[BATCH * NSLOT * QDIM];
__device__ float g_upd[BATCH * NSLOT * QDIM];
__device__ float g_vsum[BATCH * QDIM];
__device__ float g_numP[(size_t)BATCH * 128 * NSLOT * QDIM];
__device__ float g_denP[BATCH * 128 * NSLOT];

// ---- f32x2 helpers ----
__device__ __forceinline__ unsigned long long dup2(float x) {
    unsigned int u = __float_as_uint(x);
    unsigned long long r;
    asm("mov.b64 %0, {%1, %1};" : "=l"(r) : "r"(u));
    return r;
}
__device__ __forceinline__ void fma2(unsigned long long& a, unsigned long long x,
                                     unsigned long long y) {
    asm("fma.rn.f32x2 %0, %1, %2, %0;" : "+l"(a) : "l"(x), "l"(y));
}
__device__ __forceinline__ float2 unpk(unsigned long long v) {
    unsigned int lo, hi;
    asm("mov.b64 {%0, %1}, %2;" : "=r"(lo), "=r"(hi) : "l"(v));
    return make_float2(__uint_as_float(lo), __uint_as_float(hi));
}

// ---- weight prep: transpose conv weights to [kk][ic][oc], kv to [c][j], gru to [c][j] ----
__global__ void prep_weights(const float* __restrict__ c1w, const float* __restrict__ c2w,
                             const float* __restrict__ c3w, const float* __restrict__ kw,
                             const float* __restrict__ vw, const float* __restrict__ wih,
                             const float* __restrict__ whh) {
    int i = blockIdx.x * blockDim.x + threadIdx.x;
    if (i < 25 * 5 * 64) {  // 8000
        int kk = i / 320, r = i % 320, ic = r >> 6, oc = r & 63;
        g_Wt1[i] = c1w[(oc * 5 + ic) * 25 + kk];
    }
    if (i < 25 * 64 * 64) {  // 102400
        int kk = i / 4096, r = i % 4096, ic = r >> 6, oc = r & 63;
        g_Wt2[i] = c2w[(oc * 64 + ic) * 25 + kk];
        g_Wt3[i] = c3w[(oc * 64 + ic) * 25 + kk];
    }
    if (i < 64 * 128) {  // 8192
        int c = i >> 7, j = i & 127;
        g_WkvT[i] = (j < 64) ? kw[j * 64 + c] : vw[(j - 64) * 64 + c];
    }
    if (i < 2 * 192 * 64) {  // 24576
        int which = i / 12288, r = i % 12288, j = r / 64, c = r % 64;
        g_WgruT[which * 12288 + c * 192 + j] = (which ? whh : wih)[j * 64 + c];
    }
}

// ---- conv 5x5 pad2: 25 shifted GEMMs, tile 64oc x 128pos per block ----
template <int ICT, bool RELU, int XSEL, int YSEL, int WSEL>
__global__ __launch_bounds__(256, 2) void conv5x5_kernel(
    const float* __restrict__ Xp, const float* __restrict__ bias) {
    const float* X = (XSEL == 0) ? Xp : ((XSEL == 1) ? g_bufA : g_bufB);
    float* Y = (YSEL == 1) ? g_bufA : g_bufB;
    const float* Wt = (WSEL == 1) ? g_Wt1 : ((WSEL == 2) ? g_Wt2 : g_Wt3);
    constexpr int CH = (ICT < 32) ? ICT : 32;
    __shared__ __align__(16) float Xs[CH][128];
    __shared__ __align__(16) float Ws[CH][64];
    const int b = blockIdx.y, y = blockIdx.x, tid = threadIdx.x;
    const int oc0 = (tid >> 4) * 4, p0 = (tid & 15) * 8;

    unsigned long long acc[4][4];
#pragma unroll
    for (int i = 0; i < 4; i++)
#pragma unroll
        for (int j = 0; j < 4; j++) acc[i][j] = 0ull;

    for (int kh = 0; kh < 5; kh++) {
        const int iy = y + kh - 2;
        const bool rv = (iy >= 0 && iy < 128);
        for (int kw = 0; kw < 5; kw++) {
            const float* wb = Wt + (kh * 5 + kw) * ICT * 64;
            for (int ic0 = 0; ic0 < ICT; ic0 += CH) {
                __syncthreads();
                for (int i = tid; i < CH * 128; i += 256) {
                    int icl = i >> 7, c = i & 127, sx = c + kw - 2;
                    float v = 0.f;
                    if (rv && sx >= 0 && sx < 128)
                        v = X[(((size_t)b * ICT + ic0 + icl) * 128 + iy) * 128 + sx];
                    Xs[icl][c] = v;
                }
                const float* wb2 = wb + ic0 * 64;
                for (int i = tid; i < CH * 64; i += 256) Ws[i >> 6][i & 63] = wb2[i];
                __syncthreads();
#pragma unroll 4
                for (int icl = 0; icl < CH; icl++) {
                    float4 w = *(const float4*)&Ws[icl][oc0];
                    ulonglong2 bA = *(const ulonglong2*)&Xs[icl][p0];
                    ulonglong2 bB = *(const ulonglong2*)&Xs[icl][p0 + 4];
                    unsigned long long bb[4] = {bA.x, bA.y, bB.x, bB.y};
                    float wv[4] = {w.x, w.y, w.z, w.w};
#pragma unroll
                    for (int i = 0; i < 4; i++) {
                        unsigned long long a = dup2(wv[i]);
#pragma unroll
                        for (int j = 0; j < 4; j++) fma2(acc[i][j], a, bb[j]);
                    }
                }
            }
        }
    }
#pragma unroll
    for (int i = 0; i < 4; i++) {
        int oc = oc0 + i;
        float bv = bias[oc], o[8];
#pragma unroll
        for (int j = 0; j < 4; j++) {
            float2 p = unpk(acc[i][j]);
            o[2 * j] = p.x + bv;
            o[2 * j + 1] = p.y + bv;
        }
        if (RELU)
#pragma unroll
            for (int j = 0; j < 8; j++) o[j] = fmaxf(o[j], 0.f);
        float* dst = Y + (((size_t)b * 64 + oc) * 128 + y) * 128 + p0;
        *(float4*)dst = make_float4(o[0], o[1], o[2], o[3]);
        *(float4*)(dst + 4) = make_float4(o[4], o[5], o[6], o[7]);
    }
}

// ---- LayerNorm(HID=64) + keys/vals projection: 128pos x 128j per block ----
__global__ __launch_bounds__(256) void lnkv_kernel(
    const float* __restrict__ gv, const float* __restrict__ bv,
    const float* __restrict__ kb, const float* __restrict__ vb) {
    __shared__ __align__(16) float Xs[64 * 128];
    const int b = blockIdx.y, pbase = blockIdx.x * 128, tid = threadIdx.x;
    const float* eb = g_bufA + (size_t)b * 64 * NPOS + pbase;
    for (int i = tid; i < 64 * 128; i += 256) {
        int c = i >> 7, p = i & 127;
        Xs[c * 128 + p] = eb[(size_t)c * NPOS + p];
    }
    __syncthreads();
    if (tid < 128) {
        const int p = tid;
        float s = 0.f, s2 = 0.f;
#pragma unroll 8
        for (int c = 0; c < 64; c++) {
            float x = Xs[c * 128 + p];
            s += x;
            s2 += x * x;
        }
        float m = s * (1.f / 64.f);
        float var = s2 * (1.f / 64.f) - m * m;
        float rs = rsqrtf(var + 1e-5f);
#pragma unroll 8
        for (int c = 0; c < 64; c++)
            Xs[c * 128 + p] = (Xs[c * 128 + p] - m) * rs * __ldg(&gv[c]) + __ldg(&bv[c]);
    }
    __syncthreads();
    const int j0 = (tid >> 4) * 8, p0 = (tid & 15) * 8;
    unsigned long long acc[8][4];
#pragma unroll
    for (int i = 0; i < 8; i++)
#pragma unroll
        for (int j = 0; j < 4; j++) acc[i][j] = 0ull;
#pragma unroll 4
    for (int c = 0; c < 64; c++) {
        float4 w0 = __ldg((const float4*)&g_WkvT[c * 128 + j0]);
        float4 w1 = __ldg((const float4*)&g_WkvT[c * 128 + j0 + 4]);
        ulonglong2 bA = *(const ulonglong2*)&Xs[c * 128 + p0];
        ulonglong2 bB = *(const ulonglong2*)&Xs[c * 128 + p0 + 4];
        unsigned long long bb[4] = {bA.x, bA.y, bB.x, bB.y};
        float wv[8] = {w0.x, w0.y, w0.z, w0.w, w1.x, w1.y, w1.z, w1.w};
#pragma unroll
        for (int i = 0; i < 8; i++) {
            unsigned long long a = dup2(wv[i]);
#pragma unroll
            for (int j = 0; j < 4; j++) fma2(acc[i][j], a, bb[j]);
        }
    }
    const bool isK = (j0 < 64);
    float* outp = isK ? g_keys : g_vals;
    const int jj0 = isK ? j0 : (j0 - 64);
    const float* bp = isK ? kb : vb;
    float b8[8];
#pragma unroll
    for (int i = 0; i < 8; i++) b8[i] = bp[jj0 + i];
#pragma unroll
    for (int pp = 0; pp < 8; pp++) {
        float o[8];
#pragma unroll
        for (int i = 0; i < 8; i++) {
            float2 v = unpk(acc[i][pp >> 1]);
            o[i] = ((pp & 1) ? v.y : v.x) + b8[i];
        }
        float* dst = outp + ((size_t)b * NPOS + pbase + p0 + pp) * 64 + jj0;
        *(float4*)dst = make_float4(o[0], o[1], o[2], o[3]);
        *(float4*)(dst + 4) = make_float4(o[4], o[5], o[6], o[7]);
    }
}

// ---- vals column-sum ----
__global__ void vsum_kernel() {
    int b = blockIdx.x, tid = threadIdx.x, qd = tid & 63, grp = tid >> 6;
    float s = 0.f;
    for (int n = grp; n < NPOS; n += 4) s += g_vals[((size_t)b * NPOS + n) * 64 + qd];
    __shared__ float sm[256];
    sm[tid] = s;
    __syncthreads();
    if (tid < 64) g_vsum[b * 64 + tid] = sm[tid] + sm[tid + 64] + sm[tid + 128] + sm[tid + 192];
}

__global__ void copy_kernel(const float* __restrict__ src, int n) {
    int i = blockIdx.x * blockDim.x + threadIdx.x;
    if (i < n) g_qbuf[i] = src[i];
}

__global__ void diag_kernel(float* __restrict__ out, int n, float code) {
    int i = blockIdx.x * blockDim.x + threadIdx.x;
    if (i < n) out[i] = code;
}

// ---- slot LayerNorm, pre-scaled by 10/sqrt(Q)=1.25 ----
__global__ void qnorm_kernel(const float* __restrict__ g, const float* __restrict__ bb) {
    int row = blockIdx.x, d = threadIdx.x;
    float x = g_qbuf[row * 64 + d];
    float su = x, sq = x * x;
    for (int off = 16; off; off >>= 1) {
        su += __shfl_xor_sync(0xffffffffu, su, off);
        sq += __shfl_xor_sync(0xffffffffu, sq, off);
    }
    __shared__ float s0[2], s1[2];
    if ((d & 31) == 0) {
        s0[d >> 5] = su;
        s1[d >> 5] = sq;
    }
    __syncthreads();
    float ts = s0[0] + s0[1], tq = s1[0] + s1[1];
    float m = ts * (1.f / 64.f);
    float v = tq * (1.f / 64.f) - m * m;
    g_qn[row * 64 + d] = ((x - m) * rsqrtf(v + 1e-5f) * g[d] + bb[d]) * 1.25f;
}

// ---- attention: logits + softmax over slots + partial num/den ----
__global__ __launch_bounds__(256) void attn_kernel() {
    const int b = blockIdx.y, ch = blockIdx.x, tid = threadIdx.x;
    const int w = tid >> 5, l = tid & 31;
    __shared__ __align__(16) float qs[NSLOT * 64];
    for (int i = tid; i < NSLOT * 64; i += 256) qs[i] = g_qn[b * NSLOT * 64 + i];
    __syncthreads();
    float n0[NSLOT], n1[NSLOT], den[NSLOT];
#pragma unroll
    for (int s = 0; s < NSLOT; s++) n0[s] = n1[s] = den[s] = 0.f;
    const int nbase = ch * 1024 + w * 128;
    const float2* kp = (const float2*)(g_keys + ((size_t)b * NPOS + nbase) * 64) + l;
    const float2* vp = (const float2*)(g_vals + ((size_t)b * NPOS + nbase) * 64) + l;
    float2 qq[NSLOT];
#pragma unroll
    for (int s = 0; s < NSLOT; s++) qq[s] = *(const float2*)&qs[s * 64 + 2 * l];
    for (int i = 0; i < 128; i++) {
        float2 kk = kp[i * 32], vv = vp[i * 32];
        float lg[NSLOT];
#pragma unroll
        for (int s = 0; s < NSLOT; s++) {
            float p = kk.x * qq[s].x + kk.y * qq[s].y;
            p += __shfl_xor_sync(0xffffffffu, p, 16);
            p += __shfl_xor_sync(0xffffffffu, p, 8);
            p += __shfl_xor_sync(0xffffffffu, p, 4);
            p += __shfl_xor_sync(0xffffffffu, p, 2);
            p += __shfl_xor_sync(0xffffffffu, p, 1);
            lg[s] = p;
        }
        float mx = lg[0];
#pragma unroll
        for (int s = 1; s < NSLOT; s++) mx = fmaxf(mx, lg[s]);
        float e[NSLOT], sum = 0.f;
#pragma unroll
        for (int s = 0; s < NSLOT; s++) {
            e[s] = __expf(lg[s] - mx);
            sum += e[s];
        }
        float inv = 1.f / sum;
#pragma unroll
        for (int s = 0; s < NSLOT; s++) {
            float a = e[s] * inv;
            den[s] += a;
            n0[s] += a * vv.x;
            n1[s] += a * vv.y;
        }
    }
    size_t base = (size_t)b * 128 + ch * 8 + w;
    float* np = g_numP + base * (NSLOT * 64);
#pragma unroll
    for (int s = 0; s < NSLOT; s++)
        *(float2*)&np[s * 64 + 2 * l] = make_float2(n0[s], n1[s]);
    if (l == 0)
#pragma unroll
        for (int s = 0; s < NSLOT; s++) g_denP[base * NSLOT + s] = den[s];
}

// ---- reduce partials -> upd ----
__global__ void reduce_upd_kernel() {
    const int b = blockIdx.x, tid = threadIdx.x;  // 448 threads
    const int s = tid / 64, d = tid % 64;
    float den = 0.f, num = 0.f;
    for (int i = 0; i < 128; i++) {
        den += g_denP[((size_t)b * 128 + i) * NSLOT + s];
        num += g_numP[((size_t)b * 128 + i) * (NSLOT * 64) + tid];
    }
    g_upd[b * 448 + tid] = num / den + 1e-8f * g_vsum[b * 64 + d];
}

// ---- GRU + LN + FF (q in place) ----
__device__ __forceinline__ float sigm(float x) { return 1.f / (1.f + __expf(-x)); }
__global__ __launch_bounds__(256) void gru_ff_kernel(
    const float* __restrict__ bih, const float* __restrict__ bhh,
    const float* __restrict__ ug, const float* __restrict__ ub,
    const float* __restrict__ f1w, const float* __restrict__ f1b,
    const float* __restrict__ f2w, const float* __restrict__ f2b) {
    __shared__ float ups[448], hs[448], hns[448], lnh[448];
    __shared__ float gis[1344], ghs[1344], f1s[112], mv[14];
    const int b = blockIdx.x, tid = threadIdx.x;
    for (int i = tid; i < 448; i += 256) {
        ups[i] = g_upd[b * 448 + i];
        hs[i] = g_qbuf[b * 448 + i];
    }
    __syncthreads();
    for (int idx = tid; idx < 2688; idx += 256) {
        int which = idx >= 1344, rem = idx - which * 1344;
        int s = rem / 192, j = rem % 192;
        const float* src = which ? &hs[s * 64] : &ups[s * 64];
        const float* wt = g_WgruT + which * 12288;
        float acc = which ? bhh[j] : bih[j];
#pragma unroll 16
        for (int c = 0; c < 64; c++) acc += src[c] * __ldg(&wt[c * 192 + j]);
        (which ? ghs : gis)[rem] = acc;
    }
    __syncthreads();
    for (int idx = tid; idx < 448; idx += 256) {
        int s = idx / 64, d = idx % 64;
        float r = sigm(gis[s * 192 + d] + ghs[s * 192 + d]);
        float z = sigm(gis[s * 192 + 64 + d] + ghs[s * 192 + 64 + d]);
        float nn = tanhf(gis[s * 192 + 128 + d] + r * ghs[s * 192 + 128 + d]);
        hns[idx] = (1.f - z) * nn + z * hs[idx];
    }
    __syncthreads();
    if (tid < 224) {
        int s = tid >> 5, l = tid & 31;
        float x0 = hns[s * 64 + l], x1 = hns[s * 64 + 32 + l];
        float su = x0 + x1, sq = x0 * x0 + x1 * x1;
        for (int off = 16; off; off >>= 1) {
            su += __shfl_xor_sync(0xffffffffu, su, off);
            sq += __shfl_xor_sync(0xffffffffu, sq, off);
        }
        if (l == 0) {
            float m = su * (1.f / 64.f);
            float v = sq * (1.f / 64.f) - m * m;
            mv[s * 2] = m;
            mv[s * 2 + 1] = rsqrtf(v + 1e-5f);
        }
    }
    __syncthreads();
    for (int idx = tid; idx < 448; idx += 256) {
        int s = idx / 64, d = idx % 64;
        lnh[idx] = (hns[idx] - mv[s * 2]) * mv[s * 2 + 1] * ug[d] + ub[d];
    }
    __syncthreads();
    for (int idx = tid; idx < 112; idx += 256) {
        int s = idx / 16, k = idx % 16;
        float acc = f1b[k];
#pragma unroll 16
        for (int d = 0; d < 64; d++) acc += lnh[s * 64 + d] * f1w[k * 64 + d];
        f1s[idx] = fmaxf(acc, 0.f);
    }
    __syncthreads();
    for (int idx = tid; idx < 448; idx += 256) {
        int s = idx / 64, d = idx % 64;
        float acc = f2b[d];
#pragma unroll
        for (int k = 0; k < 16; k++) acc += f1s[s * 16 + k] * f2w[d * 16 + k];
        g_qbuf[b * 448 + idx] = hns[idx] + acc;
    }
}

// ---- final projection + output ----
__global__ void final_kernel(const float* __restrict__ fw, const float* __restrict__ fb,
                             float* __restrict__ out, int out_size) {
    const int b = blockIdx.x, tid = threadIdx.x;  // 512 threads
    if (tid < 448) {
        int oi = BATCH * NSLOT * 2 + b * 448 + tid;
        if (oi < out_size) out[oi] = g_qbuf[b * 448 + tid];
    } else if (tid < 448 + NSLOT * 2) {
        int idx = tid - 448, s = idx >> 1, o = idx & 1;
        float acc = fb[o];
#pragma unroll 16
        for (int d = 0; d < 64; d++) acc += g_qbuf[b * 448 + s * 64 + d] * fw[o * 64 + d];
        int oi = (b * NSLOT + s) * 2 + o;
        if (oi < out_size) out[oi] = acc;
    }
}

// Correct element counts (HID=64), reference-signature (insertion) order.
static const int SZ_INS[28] = {2621440, 14336, 8000, 64, 102400, 64, 102400, 64,
                               64, 64, 64, 64, 64, 64, 4096, 64, 4096, 64,
                               12288, 12288, 192, 192, 1024, 16, 1024, 64, 128, 2};
// Same tensors sorted alphabetically by name.
static const int SZ_ALPHA[28] = {64, 8000, 64, 102400, 64, 102400, 2621440, 64,
                                 64, 16, 1024, 64, 1024, 2, 128, 192, 192, 12288,
                                 12288, 64, 64, 14336, 64, 4096, 64, 4096, 64, 64};
// logical (insertion) index -> alphabetical position
static const int MAP_ALPHA[28] = {6, 21, 1, 0, 3, 2, 5, 4, 8, 7, 20, 19, 27, 26,
                                  23, 22, 25, 24, 18, 17, 16, 15, 10, 9, 12, 11, 14, 13};

extern "C" void kernel_launch(void* const* d_in, const int* in_sizes, int n_in,
                              void* d_out, int out_size) {
    float* out = (float*)d_out;
    const float* in[28];
    bool resolved = false;

    if (n_in >= 28) {
        for (int s = 1; s <= 4 && !resolved; s *= 4) {
            bool ins = true, alpha = true;
            for (int i = 0; i < 28; i++) {
                if (in_sizes[i] != SZ_INS[i] * s) ins = false;
                if (in_sizes[i] != SZ_ALPHA[i] * s) alpha = false;
            }
            if (ins) {
                for (int i = 0; i < 28; i++) in[i] = (const float*)d_in[i];
                resolved = true;
            } else if (alpha) {
                for (int i = 0; i < 28; i++) in[i] = (const float*)d_in[MAP_ALPHA[i]];
                resolved = true;
            }
        }
        for (int s = 1; s <= 4 && !resolved; s *= 4) {
            bool used[64];
            for (int k = 0; k < 64; k++) used[k] = false;
            bool okk = true;
            for (int i = 0; i < 28 && okk; i++) {
                int j = -1;
                for (int k = 0; k < n_in && k < 64; k++)
                    if (!used[k] && in_sizes[k] == SZ_INS[i] * s) { j = k; break; }
                if (j < 0) okk = false;
                else { used[j] = true; in[i] = (const float*)d_in[j]; }
            }
            if (okk) resolved = true;
        }
    }
    if (!resolved) {
        float code = (float)((double)n_in * 1e6 + (double)(n_in > 0 ? (in_sizes[0] % 1000000) : 0));
        diag_kernel<<<(out_size + 255) / 256, 256>>>(out, out_size, code);
        return;
    }

    const float* data = in[0];
    const float* slots = in[1];
    const float* c1b = in[3];
    const float* c2b = in[5];
    const float* c3b = in[7];
    const float* dng = in[8];
    const float* dnb = in[9];
    const float* qng = in[10];
    const float* qnb = in[11];
    const float* ung = in[12];
    const float* unb = in[13];
    const float* tkb = in[15];
    const float* tvb = in[17];
    const float* bih = in[20];
    const float* bhh = in[21];
    const float* f1w = in[22];
    const float* f1b = in[23];
    const float* f2w = in[24];
    const float* f2b = in[25];
    const float* fw = in[26];
    const float* fb = in[27];

    prep_weights<<<400, 256>>>(in[2], in[4], in[6], in[14], in[16], in[18], in[19]);
    conv5x5_kernel<5, true, 0, 1, 1><<<dim3(128, 32), 256>>>(data, c1b);
    conv5x5_kernel<64, true, 1, 2, 2><<<dim3(128, 32), 256>>>(nullptr, c2b);
    conv5x5_kernel<64, false, 2, 1, 3><<<dim3(128, 32), 256>>>(nullptr, c3b);
    lnkv_kernel<<<dim3(128, 32), 256>>>(dng, dnb, tkb, tvb);
    vsum_kernel<<<32, 256>>>();
    copy_kernel<<<56, 256>>>(slots, BATCH * NSLOT * QDIM);
    for (int it = 0; it < 3; it++) {
        qnorm_kernel<<<BATCH * NSLOT, 64>>>(qng, qnb);
        attn_kernel<<<dim3(16, BATCH), 256>>>();
        reduce_upd_kernel<<<BATCH, 448>>>();
        gru_ff_kernel<<<BATCH, 256>>>(bih, bhh, ung, unb, f1w, f1b, f2w, f2b);
    }
    final_kernel<<<BATCH, 512>>>(fw, fb, out, out_size);
}

// round 10
// speedup vs baseline: 1.5186x; 1.5186x over previous
#include <cuda_runtime.h>
#include <cstdint>

#define BATCH 32
#define NSLOT 7
#define QDIM 64
#define HID 64
#define NPOS 16384

// ---- scratch (device globals; no allocation) ----
__device__ float g_bufA[(size_t)BATCH * HID * NPOS];
__device__ float g_bufB[(size_t)BATCH * HID * NPOS];
__device__ float g_keys[(size_t)BATCH * NPOS * QDIM];
__device__ float g_vals[(size_t)BATCH * NPOS * QDIM];
__device__ float g_Wt1[25 * 5 * HID];
__device__ float g_Wt2[25 * HID * HID];
__device__ float g_Wt3[25 * HID * HID];
__device__ float g_WkvT[HID * 128];
__device__ float g_WgruT[2 * 64 * 192];
__device__ float g_qbuf[BATCH * NSLOT * QDIM];
__device__ float g_qn[BATCH * NSLOT * QDIM];
__device__ float g_upd[BATCH * NSLOT * QDIM];
__device__ float g_vsum[BATCH * QDIM];
__device__ float g_numP[(size_t)BATCH * 128 * NSLOT * QDIM];
__device__ float g_denP[BATCH * 128 * NSLOT];

// ---- f32x2 helpers ----
__device__ __forceinline__ unsigned long long dup2(float x) {
    unsigned int u = __float_as_uint(x);
    unsigned long long r;
    asm("mov.b64 %0, {%1, %1};" : "=l"(r) : "r"(u));
    return r;
}
__device__ __forceinline__ unsigned long long pack2(float lo, float hi) {
    unsigned long long r;
    asm("mov.b64 %0, {%1, %2};" : "=l"(r) : "r"(__float_as_uint(lo)), "r"(__float_as_uint(hi)));
    return r;
}
__device__ __forceinline__ void fma2(unsigned long long& a, unsigned long long x,
                                     unsigned long long y) {
    asm("fma.rn.f32x2 %0, %1, %2, %0;" : "+l"(a) : "l"(x), "l"(y));
}
__device__ __forceinline__ float2 unpk(unsigned long long v) {
    unsigned int lo, hi;
    asm("mov.b64 {%0, %1}, %2;" : "=r"(lo), "=r"(hi) : "l"(v));
    return make_float2(__uint_as_float(lo), __uint_as_float(hi));
}

// ---- cp.async helpers ----
__device__ __forceinline__ uint32_t s2u(const void* p) {
    uint32_t a;
    asm("{ .reg .u64 t; cvta.to.shared.u64 t, %1; cvt.u32.u64 %0, t; }" : "=r"(a) : "l"(p));
    return a;
}
__device__ __forceinline__ void cpa8z(uint32_t d, const float* s, bool v) {
    int sz = v ? 8 : 0;
    asm volatile("cp.async.ca.shared.global [%0], [%1], 8, %2;" :: "r"(d), "l"(s), "r"(sz));
}
__device__ __forceinline__ void cpa16(uint32_t d, const float* s) {
    asm volatile("cp.async.cg.shared.global [%0], [%1], 16;" :: "r"(d), "l"(s));
}

// ---- weight prep ----
__global__ void prep_weights(const float* __restrict__ c1w, const float* __restrict__ c2w,
                             const float* __restrict__ c3w, const float* __restrict__ kw,
                             const float* __restrict__ vw, const float* __restrict__ wih,
                             const float* __restrict__ whh) {
    int i = blockIdx.x * blockDim.x + threadIdx.x;
    if (i < 25 * 5 * 64) {
        int kk = i / 320, r = i % 320, ic = r >> 6, oc = r & 63;
        g_Wt1[i] = c1w[(oc * 5 + ic) * 25 + kk];
    }
    if (i < 25 * 64 * 64) {
        int kk = i / 4096, r = i % 4096, ic = r >> 6, oc = r & 63;
        g_Wt2[i] = c2w[(oc * 64 + ic) * 25 + kk];
        g_Wt3[i] = c3w[(oc * 64 + ic) * 25 + kk];
    }
    if (i < 64 * 128) {
        int c = i >> 7, j = i & 127;
        g_WkvT[i] = (j < 64) ? kw[j * 64 + c] : vw[(j - 64) * 64 + c];
    }
    if (i < 2 * 192 * 64) {
        int which = i / 12288, r = i % 12288, j = r / 64, c = r % 64;
        g_WgruT[which * 12288 + c * 192 + j] = (which ? whh : wih)[j * 64 + c];
    }
}

// ---- conv 5x5 pad2: kw-hoisted shifted GEMM, cp.async double-buffered ----
// One block: 64 oc x 128 positions for one (b, y). Phases over (kh, ic-chunk).
template <int ICT, bool RELU, int XSEL, int YSEL, int WSEL>
__global__ __launch_bounds__(256, 2) void conv5x5_kernel(
    const float* __restrict__ Xp, const float* __restrict__ bias) {
    const float* X = (XSEL == 0) ? Xp : ((XSEL == 1) ? g_bufA : g_bufB);
    float* Y = (YSEL == 1) ? g_bufA : g_bufB;
    const float* Wt = (WSEL == 1) ? g_Wt1 : ((WSEL == 2) ? g_Wt2 : g_Wt3);
    constexpr int CH = (ICT < 8) ? ICT : 8;
    constexpr int NCH = ICT / CH;
    constexpr int NPH = 5 * NCH;
    __shared__ __align__(16) float Xs[2][CH][136];   // halo'd row: col c stored at c+2
    __shared__ __align__(16) float Ws[2][CH * 5 * 64];
    const int b = blockIdx.y, y = blockIdx.x, tid = threadIdx.x;
    const int oc0 = (tid >> 4) * 4, p0 = (tid & 15) * 8;

    // zero halo words once (cp.async never touches them)
    for (int i = tid; i < 2 * CH * 8; i += 256) {
        int bufi = i / (CH * 8), r = i % (CH * 8), icl = r >> 3, k = r & 7;
        int c = (k < 2) ? k : (128 + k);  // 0,1,130..135
        Xs[bufi][icl][c] = 0.f;
    }
    __syncthreads();

    auto issue = [&](int ph, int bufi) {
        const int kh = ph / NCH, ic0 = (ph % NCH) * CH;
        const int iy = y + kh - 2;
        const bool rv = (iy >= 0) && (iy < 128);
        for (int i = tid; i < CH * 64; i += 256) {            // X row: 8B ops
            int icl = i >> 6, c2 = (i & 63) * 2;
            uint32_t dst = s2u(&Xs[bufi][icl][2 + c2]);
            const float* src = X + (((size_t)b * ICT + ic0 + icl) * 128 + iy) * 128 + c2;
            cpa8z(dst, src, rv);
        }
        for (int i = tid; i < CH * 5 * 16; i += 256) {        // W: 16B ops
            int icl = i / 80, r = i % 80, kw = r / 16, q = r % 16;
            uint32_t dst = s2u(&Ws[bufi][(icl * 5 + kw) * 64 + q * 4]);
            const float* src = Wt + ((size_t)((kh * 5 + kw) * ICT) + ic0 + icl) * 64 + q * 4;
            cpa16(dst, src);
        }
        asm volatile("cp.async.commit_group;");
    };

    unsigned long long acc[4][4];
#pragma unroll
    for (int i = 0; i < 4; i++)
#pragma unroll
        for (int j = 0; j < 4; j++) acc[i][j] = 0ull;

    issue(0, 0);
    for (int ph = 0; ph < NPH; ph++) {
        const int bufi = ph & 1;
        if (ph + 1 < NPH) {
            issue(ph + 1, bufi ^ 1);
            asm volatile("cp.async.wait_group 1;");
        } else {
            asm volatile("cp.async.wait_group 0;");
        }
        __syncthreads();
#pragma unroll
        for (int icl = 0; icl < CH; icl++) {
            const float4 xa = *(const float4*)&Xs[bufi][icl][p0];
            const float4 xb = *(const float4*)&Xs[bufi][icl][p0 + 4];
            const float4 xc = *(const float4*)&Xs[bufi][icl][p0 + 8];
            const float x[12] = {xa.x, xa.y, xa.z, xa.w, xb.x, xb.y, xb.z, xb.w,
                                 xc.x, xc.y, xc.z, xc.w};
            unsigned long long pr[11];
#pragma unroll
            for (int s = 0; s < 11; s++) pr[s] = pack2(x[s], x[s + 1]);
#pragma unroll
            for (int kw = 0; kw < 5; kw++) {
                const float4 w = *(const float4*)&Ws[bufi][(icl * 5 + kw) * 64 + oc0];
                const float wv[4] = {w.x, w.y, w.z, w.w};
#pragma unroll
                for (int i = 0; i < 4; i++) {
                    unsigned long long a = dup2(wv[i]);
                    fma2(acc[i][0], a, pr[kw]);
                    fma2(acc[i][1], a, pr[kw + 2]);
                    fma2(acc[i][2], a, pr[kw + 4]);
                    fma2(acc[i][3], a, pr[kw + 6]);
                }
            }
        }
        __syncthreads();  // done reading bufi before it is refilled at ph+2
    }

#pragma unroll
    for (int i = 0; i < 4; i++) {
        int oc = oc0 + i;
        float bv = bias[oc], o[8];
#pragma unroll
        for (int j = 0; j < 4; j++) {
            float2 p = unpk(acc[i][j]);
            o[2 * j] = p.x + bv;
            o[2 * j + 1] = p.y + bv;
        }
        if (RELU)
#pragma unroll
            for (int j = 0; j < 8; j++) o[j] = fmaxf(o[j], 0.f);
        float* dst = Y + (((size_t)b * 64 + oc) * 128 + y) * 128 + p0;
        *(float4*)dst = make_float4(o[0], o[1], o[2], o[3]);
        *(float4*)(dst + 4) = make_float4(o[4], o[5], o[6], o[7]);
    }
}

// ---- LayerNorm(HID=64) + keys/vals projection: 128pos x 128j per block ----
__global__ __launch_bounds__(256) void lnkv_kernel(
    const float* __restrict__ gv, const float* __restrict__ bv,
    const float* __restrict__ kb, const float* __restrict__ vb) {
    __shared__ __align__(16) float Xs[64 * 128];
    const int b = blockIdx.y, pbase = blockIdx.x * 128, tid = threadIdx.x;
    const float* eb = g_bufA + (size_t)b * 64 * NPOS + pbase;
    for (int i = tid; i < 64 * 128; i += 256) {
        int c = i >> 7, p = i & 127;
        Xs[c * 128 + p] = eb[(size_t)c * NPOS + p];
    }
    __syncthreads();
    if (tid < 128) {
        const int p = tid;
        float s = 0.f, s2 = 0.f;
#pragma unroll 8
        for (int c = 0; c < 64; c++) {
            float x = Xs[c * 128 + p];
            s += x;
            s2 += x * x;
        }
        float m = s * (1.f / 64.f);
        float var = s2 * (1.f / 64.f) - m * m;
        float rs = rsqrtf(var + 1e-5f);
#pragma unroll 8
        for (int c = 0; c < 64; c++)
            Xs[c * 128 + p] = (Xs[c * 128 + p] - m) * rs * __ldg(&gv[c]) + __ldg(&bv[c]);
    }
    __syncthreads();
    const int j0 = (tid >> 4) * 8, p0 = (tid & 15) * 8;
    unsigned long long acc[8][4];
#pragma unroll
    for (int i = 0; i < 8; i++)
#pragma unroll
        for (int j = 0; j < 4; j++) acc[i][j] = 0ull;
#pragma unroll 4
    for (int c = 0; c < 64; c++) {
        float4 w0 = __ldg((const float4*)&g_WkvT[c * 128 + j0]);
        float4 w1 = __ldg((const float4*)&g_WkvT[c * 128 + j0 + 4]);
        ulonglong2 bA = *(const ulonglong2*)&Xs[c * 128 + p0];
        ulonglong2 bB = *(const ulonglong2*)&Xs[c * 128 + p0 + 4];
        unsigned long long bb[4] = {bA.x, bA.y, bB.x, bB.y};
        float wv[8] = {w0.x, w0.y, w0.z, w0.w, w1.x, w1.y, w1.z, w1.w};
#pragma unroll
        for (int i = 0; i < 8; i++) {
            unsigned long long a = dup2(wv[i]);
#pragma unroll
            for (int j = 0; j < 4; j++) fma2(acc[i][j], a, bb[j]);
        }
    }
    const bool isK = (j0 < 64);
    float* outp = isK ? g_keys : g_vals;
    const int jj0 = isK ? j0 : (j0 - 64);
    const float* bp = isK ? kb : vb;
    float b8[8];
#pragma unroll
    for (int i = 0; i < 8; i++) b8[i] = bp[jj0 + i];
#pragma unroll
    for (int pp = 0; pp < 8; pp++) {
        float o[8];
#pragma unroll
        for (int i = 0; i < 8; i++) {
            float2 v = unpk(acc[i][pp >> 1]);
            o[i] = ((pp & 1) ? v.y : v.x) + b8[i];
        }
        float* dst = outp + ((size_t)b * NPOS + pbase + p0 + pp) * 64 + jj0;
        *(float4*)dst = make_float4(o[0], o[1], o[2], o[3]);
        *(float4*)(dst + 4) = make_float4(o[4], o[5], o[6], o[7]);
    }
}

// ---- vals column-sum ----
__global__ void vsum_kernel() {
    int b = blockIdx.x, tid = threadIdx.x, qd = tid & 63, grp = tid >> 6;
    float s = 0.f;
    for (int n = grp; n < NPOS; n += 4) s += g_vals[((size_t)b * NPOS + n) * 64 + qd];
    __shared__ float sm[256];
    sm[tid] = s;
    __syncthreads();
    if (tid < 64) g_vsum[b * 64 + tid] = sm[tid] + sm[tid + 64] + sm[tid + 128] + sm[tid + 192];
}

__global__ void copy_kernel(const float* __restrict__ src, int n) {
    int i = blockIdx.x * blockDim.x + threadIdx.x;
    if (i < n) g_qbuf[i] = src[i];
}

__global__ void diag_kernel(float* __restrict__ out, int n, float code) {
    int i = blockIdx.x * blockDim.x + threadIdx.x;
    if (i < n) out[i] = code;
}

// ---- slot LayerNorm, pre-scaled by 10/sqrt(Q)=1.25 ----
__global__ void qnorm_kernel(const float* __restrict__ g, const float* __restrict__ bb) {
    int row = blockIdx.x, d = threadIdx.x;
    float x = g_qbuf[row * 64 + d];
    float su = x, sq = x * x;
    for (int off = 16; off; off >>= 1) {
        su += __shfl_xor_sync(0xffffffffu, su, off);
        sq += __shfl_xor_sync(0xffffffffu, sq, off);
    }
    __shared__ float s0[2], s1[2];
    if ((d & 31) == 0) {
        s0[d >> 5] = su;
        s1[d >> 5] = sq;
    }
    __syncthreads();
    float ts = s0[0] + s0[1], tq = s1[0] + s1[1];
    float m = ts * (1.f / 64.f);
    float v = tq * (1.f / 64.f) - m * m;
    g_qn[row * 64 + d] = ((x - m) * rsqrtf(v + 1e-5f) * g[d] + bb[d]) * 1.25f;
}

// ---- attention: logits + softmax over slots + partial num/den ----
__global__ __launch_bounds__(256) void attn_kernel() {
    const int b = blockIdx.y, ch = blockIdx.x, tid = threadIdx.x;
    const int w = tid >> 5, l = tid & 31;
    __shared__ __align__(16) float qs[NSLOT * 64];
    for (int i = tid; i < NSLOT * 64; i += 256) qs[i] = g_qn[b * NSLOT * 64 + i];
    __syncthreads();
    float n0[NSLOT], n1[NSLOT], den[NSLOT];
#pragma unroll
    for (int s = 0; s < NSLOT; s++) n0[s] = n1[s] = den[s] = 0.f;
    const int nbase = ch * 1024 + w * 128;
    const float2* kp = (const float2*)(g_keys + ((size_t)b * NPOS + nbase) * 64) + l;
    const float2* vp = (const float2*)(g_vals + ((size_t)b * NPOS + nbase) * 64) + l;
    float2 qq[NSLOT];
#pragma unroll
    for (int s = 0; s < NSLOT; s++) qq[s] = *(const float2*)&qs[s * 64 + 2 * l];
    for (int i = 0; i < 128; i++) {
        float2 kk = kp[i * 32], vv = vp[i * 32];
        float lg[NSLOT];
#pragma unroll
        for (int s = 0; s < NSLOT; s++) {
            float p = kk.x * qq[s].x + kk.y * qq[s].y;
            p += __shfl_xor_sync(0xffffffffu, p, 16);
            p += __shfl_xor_sync(0xffffffffu, p, 8);
            p += __shfl_xor_sync(0xffffffffu, p, 4);
            p += __shfl_xor_sync(0xffffffffu, p, 2);
            p += __shfl_xor_sync(0xffffffffu, p, 1);
            lg[s] = p;
        }
        float mx = lg[0];
#pragma unroll
        for (int s = 1; s < NSLOT; s++) mx = fmaxf(mx, lg[s]);
        float e[NSLOT], sum = 0.f;
#pragma unroll
        for (int s = 0; s < NSLOT; s++) {
            e[s] = __expf(lg[s] - mx);
            sum += e[s];
        }
        float inv = 1.f / sum;
#pragma unroll
        for (int s = 0; s < NSLOT; s++) {
            float a = e[s] * inv;
            den[s] += a;
            n0[s] += a * vv.x;
            n1[s] += a * vv.y;
        }
    }
    size_t base = (size_t)b * 128 + ch * 8 + w;
    float* np = g_numP + base * (NSLOT * 64);
#pragma unroll
    for (int s = 0; s < NSLOT; s++)
        *(float2*)&np[s * 64 + 2 * l] = make_float2(n0[s], n1[s]);
    if (l == 0)
#pragma unroll
        for (int s = 0; s < NSLOT; s++) g_denP[base * NSLOT + s] = den[s];
}

// ---- reduce partials -> upd ----
__global__ void reduce_upd_kernel() {
    const int b = blockIdx.x, tid = threadIdx.x;  // 448 threads
    const int s = tid / 64, d = tid % 64;
    float den = 0.f, num = 0.f;
    for (int i = 0; i < 128; i++) {
        den += g_denP[((size_t)b * 128 + i) * NSLOT + s];
        num += g_numP[((size_t)b * 128 + i) * (NSLOT * 64) + tid];
    }
    g_upd[b * 448 + tid] = num / den + 1e-8f * g_vsum[b * 64 + d];
}

// ---- GRU + LN + FF (q in place) ----
__device__ __forceinline__ float sigm(float x) { return 1.f / (1.f + __expf(-x)); }
__global__ __launch_bounds__(256) void gru_ff_kernel(
    const float* __restrict__ bih, const float* __restrict__ bhh,
    const float* __restrict__ ug, const float* __restrict__ ub,
    const float* __restrict__ f1w, const float* __restrict__ f1b,
    const float* __restrict__ f2w, const float* __restrict__ f2b) {
    __shared__ float ups[448], hs[448], hns[448], lnh[448];
    __shared__ float gis[1344], ghs[1344], f1s[112], mv[14];
    const int b = blockIdx.x, tid = threadIdx.x;
    for (int i = tid; i < 448; i += 256) {
        ups[i] = g_upd[b * 448 + i];
        hs[i] = g_qbuf[b * 448 + i];
    }
    __syncthreads();
    for (int idx = tid; idx < 2688; idx += 256) {
        int which = idx >= 1344, rem = idx - which * 1344;
        int s = rem / 192, j = rem % 192;
        const float* src = which ? &hs[s * 64] : &ups[s * 64];
        const float* wt = g_WgruT + which * 12288;
        float acc = which ? bhh[j] : bih[j];
#pragma unroll 16
        for (int c = 0; c < 64; c++) acc += src[c] * __ldg(&wt[c * 192 + j]);
        (which ? ghs : gis)[rem] = acc;
    }
    __syncthreads();
    for (int idx = tid; idx < 448; idx += 256) {
        int s = idx / 64, d = idx % 64;
        float r = sigm(gis[s * 192 + d] + ghs[s * 192 + d]);
        float z = sigm(gis[s * 192 + 64 + d] + ghs[s * 192 + 64 + d]);
        float nn = tanhf(gis[s * 192 + 128 + d] + r * ghs[s * 192 + 128 + d]);
        hns[idx] = (1.f - z) * nn + z * hs[idx];
    }
    __syncthreads();
    if (tid < 224) {
        int s = tid >> 5, l = tid & 31;
        float x0 = hns[s * 64 + l], x1 = hns[s * 64 + 32 + l];
        float su = x0 + x1, sq = x0 * x0 + x1 * x1;
        for (int off = 16; off; off >>= 1) {
            su += __shfl_xor_sync(0xffffffffu, su, off);
            sq += __shfl_xor_sync(0xffffffffu, sq, off);
        }
        if (l == 0) {
            float m = su * (1.f / 64.f);
            float v = sq * (1.f / 64.f) - m * m;
            mv[s * 2] = m;
            mv[s * 2 + 1] = rsqrtf(v + 1e-5f);
        }
    }
    __syncthreads();
    for (int idx = tid; idx < 448; idx += 256) {
        int s = idx / 64, d = idx % 64;
        lnh[idx] = (hns[idx] - mv[s * 2]) * mv[s * 2 + 1] * ug[d] + ub[d];
    }
    __syncthreads();
    for (int idx = tid; idx < 112; idx += 256) {
        int s = idx / 16, k = idx % 16;
        float acc = f1b[k];
#pragma unroll 16
        for (int d = 0; d < 64; d++) acc += lnh[s * 64 + d] * f1w[k * 64 + d];
        f1s[idx] = fmaxf(acc, 0.f);
    }
    __syncthreads();
    for (int idx = tid; idx < 448; idx += 256) {
        int s = idx / 64, d = idx % 64;
        float acc = f2b[d];
#pragma unroll
        for (int k = 0; k < 16; k++) acc += f1s[s * 16 + k] * f2w[d * 16 + k];
        g_qbuf[b * 448 + idx] = hns[idx] + acc;
    }
}

// ---- final projection + output ----
__global__ void final_kernel(const float* __restrict__ fw, const float* __restrict__ fb,
                             float* __restrict__ out, int out_size) {
    const int b = blockIdx.x, tid = threadIdx.x;  // 512 threads
    if (tid < 448) {
        int oi = BATCH * NSLOT * 2 + b * 448 + tid;
        if (oi < out_size) out[oi] = g_qbuf[b * 448 + tid];
    } else if (tid < 448 + NSLOT * 2) {
        int idx = tid - 448, s = idx >> 1, o = idx & 1;
        float acc = fb[o];
#pragma unroll 16
        for (int d = 0; d < 64; d++) acc += g_qbuf[b * 448 + s * 64 + d] * fw[o * 64 + d];
        int oi = (b * NSLOT + s) * 2 + o;
        if (oi < out_size) out[oi] = acc;
    }
}

// Element counts (HID=64), reference-signature (insertion) order.
static const int SZ_INS[28] = {2621440, 14336, 8000, 64, 102400, 64, 102400, 64,
                               64, 64, 64, 64, 64, 64, 4096, 64, 4096, 64,
                               12288, 12288, 192, 192, 1024, 16, 1024, 64, 128, 2};
static const int SZ_ALPHA[28] = {64, 8000, 64, 102400, 64, 102400, 2621440, 64,
                                 64, 16, 1024, 64, 1024, 2, 128, 192, 192, 12288,
                                 12288, 64, 64, 14336, 64, 4096, 64, 4096, 64, 64};
static const int MAP_ALPHA[28] = {6, 21, 1, 0, 3, 2, 5, 4, 8, 7, 20, 19, 27, 26,
                                  23, 22, 25, 24, 18, 17, 16, 15, 10, 9, 12, 11, 14, 13};

extern "C" void kernel_launch(void* const* d_in, const int* in_sizes, int n_in,
                              void* d_out, int out_size) {
    float* out = (float*)d_out;
    const float* in[28];
    bool resolved = false;

    if (n_in >= 28) {
        for (int s = 1; s <= 4 && !resolved; s *= 4) {
            bool ins = true, alpha = true;
            for (int i = 0; i < 28; i++) {
                if (in_sizes[i] != SZ_INS[i] * s) ins = false;
                if (in_sizes[i] != SZ_ALPHA[i] * s) alpha = false;
            }
            if (ins) {
                for (int i = 0; i < 28; i++) in[i] = (const float*)d_in[i];
                resolved = true;
            } else if (alpha) {
                for (int i = 0; i < 28; i++) in[i] = (const float*)d_in[MAP_ALPHA[i]];
                resolved = true;
            }
        }
        for (int s = 1; s <= 4 && !resolved; s *= 4) {
            bool used[64];
            for (int k = 0; k < 64; k++) used[k] = false;
            bool okk = true;
            for (int i = 0; i < 28 && okk; i++) {
                int j = -1;
                for (int k = 0; k < n_in && k < 64; k++)
                    if (!used[k] && in_sizes[k] == SZ_INS[i] * s) { j = k; break; }
                if (j < 0) okk = false;
                else { used[j] = true; in[i] = (const float*)d_in[j]; }
            }
            if (okk) resolved = true;
        }
    }
    if (!resolved) {
        float code = (float)((double)n_in * 1e6 + (double)(n_in > 0 ? (in_sizes[0] % 1000000) : 0));
        diag_kernel<<<(out_size + 255) / 256, 256>>>(out, out_size, code);
        return;
    }

    const float* data = in[0];
    const float* slots = in[1];
    const float* c1b = in[3];
    const float* c2b = in[5];
    const float* c3b = in[7];
    const float* dng = in[8];
    const float* dnb = in[9];
    const float* qng = in[10];
    const float* qnb = in[11];
    const float* ung = in[12];
    const float* unb = in[13];
    const float* tkb = in[15];
    const float* tvb = in[17];
    const float* bih = in[20];
    const float* bhh = in[21];
    const float* f1w = in[22];
    const float* f1b = in[23];
    const float* f2w = in[24];
    const float* f2b = in[25];
    const float* fw = in[26];
    const float* fb = in[27];

    prep_weights<<<400, 256>>>(in[2], in[4], in[6], in[14], in[16], in[18], in[19]);
    conv5x5_kernel<5, true, 0, 1, 1><<<dim3(128, 32), 256>>>(data, c1b);
    conv5x5_kernel<64, true, 1, 2, 2><<<dim3(128, 32), 256>>>(nullptr, c2b);
    conv5x5_kernel<64, false, 2, 1, 3><<<dim3(128, 32), 256>>>(nullptr, c3b);
    lnkv_kernel<<<dim3(128, 32), 256>>>(dng, dnb, tkb, tvb);
    vsum_kernel<<<32, 256>>>();
    copy_kernel<<<56, 256>>>(slots, BATCH * NSLOT * QDIM);
    for (int it = 0; it < 3; it++) {
        qnorm_kernel<<<BATCH * NSLOT, 64>>>(qng, qnb);
        attn_kernel<<<dim3(16, BATCH), 256>>>();
        reduce_upd_kernel<<<BATCH, 448>>>();
        gru_ff_kernel<<<BATCH, 256>>>(bih, bhh, ung, unb, f1w, f1b, f2w, f2b);
    }
    final_kernel<<<BATCH, 512>>>(fw, fb, out, out_size);
}

// round 11
// speedup vs baseline: 1.8316x; 1.2061x over previous
#include <cuda_runtime.h>
#include <cstdint>

#define BATCH 32
#define NSLOT 7
#define QDIM 64
#define HID 64
#define NPOS 16384

// ---- scratch (device globals; no allocation) ----
__device__ float g_bufA[(size_t)BATCH * HID * NPOS];
__device__ float g_bufB[(size_t)BATCH * HID * NPOS];
__device__ float g_keys[(size_t)BATCH * NPOS * QDIM];
__device__ float g_vals[(size_t)BATCH * NPOS * QDIM];
__device__ float g_Wt1[25 * 5 * HID];
__device__ float g_Wt2[25 * HID * HID];
__device__ float g_Wt3[25 * HID * HID];
__device__ float g_WkvT[HID * 128];
__device__ float g_WgruT[2 * 64 * 192];
__device__ float g_qbuf[BATCH * NSLOT * QDIM];
__device__ float g_qn[BATCH * NSLOT * QDIM];
__device__ float g_upd[BATCH * NSLOT * QDIM];
__device__ float g_vsum[BATCH * QDIM];
__device__ float g_numP[(size_t)BATCH * 128 * NSLOT * QDIM];
__device__ float g_denP[BATCH * 128 * NSLOT];

// ---- f32x2 helpers ----
__device__ __forceinline__ unsigned long long dup2(float x) {
    unsigned int u = __float_as_uint(x);
    unsigned long long r;
    asm("mov.b64 %0, {%1, %1};" : "=l"(r) : "r"(u));
    return r;
}
__device__ __forceinline__ void fma2(unsigned long long& a, unsigned long long x,
                                     unsigned long long y) {
    asm("fma.rn.f32x2 %0, %1, %2, %0;" : "+l"(a) : "l"(x), "l"(y));
}
__device__ __forceinline__ float2 unpk(unsigned long long v) {
    unsigned int lo, hi;
    asm("mov.b64 {%0, %1}, %2;" : "=r"(lo), "=r"(hi) : "l"(v));
    return make_float2(__uint_as_float(lo), __uint_as_float(hi));
}

// ---- cp.async helpers ----
__device__ __forceinline__ uint32_t s2u(const void* p) {
    uint32_t a;
    asm("{ .reg .u64 t; cvta.to.shared.u64 t, %1; cvt.u32.u64 %0, t; }" : "=r"(a) : "l"(p));
    return a;
}
__device__ __forceinline__ void cpa8z(uint32_t d, const float* s, bool v) {
    int sz = v ? 8 : 0;
    asm volatile("cp.async.ca.shared.global [%0], [%1], 8, %2;" :: "r"(d), "l"(s), "r"(sz));
}
__device__ __forceinline__ void cpa16(uint32_t d, const float* s) {
    asm volatile("cp.async.cg.shared.global [%0], [%1], 16;" :: "r"(d), "l"(s));
}

// ---- weight prep ----
__global__ void prep_weights(const float* __restrict__ c1w, const float* __restrict__ c2w,
                             const float* __restrict__ c3w, const float* __restrict__ kw,
                             const float* __restrict__ vw, const float* __restrict__ wih,
                             const float* __restrict__ whh) {
    int i = blockIdx.x * blockDim.x + threadIdx.x;
    if (i < 25 * 5 * 64) {
        int kk = i / 320, r = i % 320, ic = r >> 6, oc = r & 63;
        g_Wt1[i] = c1w[(oc * 5 + ic) * 25 + kk];
    }
    if (i < 25 * 64 * 64) {
        int kk = i / 4096, r = i % 4096, ic = r >> 6, oc = r & 63;
        g_Wt2[i] = c2w[(oc * 64 + ic) * 25 + kk];
        g_Wt3[i] = c3w[(oc * 64 + ic) * 25 + kk];
    }
    if (i < 64 * 128) {
        int c = i >> 7, j = i & 127;
        g_WkvT[i] = (j < 64) ? kw[j * 64 + c] : vw[(j - 64) * 64 + c];
    }
    if (i < 2 * 192 * 64) {
        int which = i / 12288, r = i % 12288, j = r / 64, c = r % 64;
        g_WgruT[which * 12288 + c * 192 + j] = (which ? whh : wih)[j * 64 + c];
    }
}

// ---- conv 5x5 pad2: kw-hoisted shifted GEMM, cp.async double-buffered ----
// v3: weights consumed as natural (oc,oc+1) f32x2 pairs (no pack); x values dup2'd.
template <int ICT, bool RELU, int XSEL, int YSEL, int WSEL>
__global__ __launch_bounds__(256, 3) void conv5x5_kernel(
    const float* __restrict__ Xp, const float* __restrict__ bias) {
    const float* X = (XSEL == 0) ? Xp : ((XSEL == 1) ? g_bufA : g_bufB);
    float* Y = (YSEL == 1) ? g_bufA : g_bufB;
    const float* Wt = (WSEL == 1) ? g_Wt1 : ((WSEL == 2) ? g_Wt2 : g_Wt3);
    constexpr int CH = (ICT < 8) ? ICT : 8;
    constexpr int NCH = ICT / CH;
    constexpr int NPH = 5 * NCH;
    __shared__ __align__(16) float Xs[2][CH][136];   // halo'd row: col c stored at c+2
    __shared__ __align__(16) float Ws[2][CH * 5 * 64];
    const int b = blockIdx.y, y = blockIdx.x, tid = threadIdx.x;
    const int oc0 = (tid >> 4) * 4, p0 = (tid & 15) * 8;

    for (int i = tid; i < 2 * CH * 8; i += 256) {
        int bufi = i / (CH * 8), r = i % (CH * 8), icl = r >> 3, k = r & 7;
        int c = (k < 2) ? k : (128 + k);
        Xs[bufi][icl][c] = 0.f;
    }
    __syncthreads();

    auto issue = [&](int ph, int bufi) {
        const int kh = ph / NCH, ic0 = (ph % NCH) * CH;
        const int iy = y + kh - 2;
        const bool rv = (iy >= 0) && (iy < 128);
        for (int i = tid; i < CH * 64; i += 256) {
            int icl = i >> 6, c2 = (i & 63) * 2;
            uint32_t dst = s2u(&Xs[bufi][icl][2 + c2]);
            const float* src = X + (((size_t)b * ICT + ic0 + icl) * 128 + iy) * 128 + c2;
            cpa8z(dst, src, rv);
        }
        for (int i = tid; i < CH * 5 * 16; i += 256) {
            int icl = i / 80, r = i % 80, kw = r / 16, q = r % 16;
            uint32_t dst = s2u(&Ws[bufi][(icl * 5 + kw) * 64 + q * 4]);
            const float* src = Wt + ((size_t)((kh * 5 + kw) * ICT) + ic0 + icl) * 64 + q * 4;
            cpa16(dst, src);
        }
        asm volatile("cp.async.commit_group;");
    };

    // acc[pair][pos]: pair 0 = (oc0,oc0+1), pair 1 = (oc0+2,oc0+3)
    unsigned long long acc[2][8];
#pragma unroll
    for (int i = 0; i < 2; i++)
#pragma unroll
        for (int j = 0; j < 8; j++) acc[i][j] = 0ull;

    issue(0, 0);
    for (int ph = 0; ph < NPH; ph++) {
        const int bufi = ph & 1;
        if (ph + 1 < NPH) {
            issue(ph + 1, bufi ^ 1);
            asm volatile("cp.async.wait_group 1;");
        } else {
            asm volatile("cp.async.wait_group 0;");
        }
        __syncthreads();
#pragma unroll
        for (int icl = 0; icl < CH; icl++) {
            const float4 xa = *(const float4*)&Xs[bufi][icl][p0];
            const float4 xb = *(const float4*)&Xs[bufi][icl][p0 + 4];
            const float4 xc = *(const float4*)&Xs[bufi][icl][p0 + 8];
            const float x[12] = {xa.x, xa.y, xa.z, xa.w, xb.x, xb.y, xb.z, xb.w,
                                 xc.x, xc.y, xc.z, xc.w};
            unsigned long long xd[12];
#pragma unroll
            for (int s = 0; s < 12; s++) xd[s] = dup2(x[s]);
#pragma unroll
            for (int kw = 0; kw < 5; kw++) {
                // natural f32x2 pairs: (oc0,oc0+1) and (oc0+2,oc0+3), 16B aligned
                const ulonglong2 w = *(const ulonglong2*)&Ws[bufi][(icl * 5 + kw) * 64 + oc0];
#pragma unroll
                for (int p = 0; p < 8; p++) {
                    fma2(acc[0][p], w.x, xd[p + kw]);
                    fma2(acc[1][p], w.y, xd[p + kw]);
                }
            }
        }
        __syncthreads();
    }

#pragma unroll
    for (int i = 0; i < 4; i++) {
        const int pair = i >> 1, hi = i & 1;
        int oc = oc0 + i;
        float bv = bias[oc], o[8];
#pragma unroll
        for (int p = 0; p < 8; p++) {
            float2 v = unpk(acc[pair][p]);
            o[p] = (hi ? v.y : v.x) + bv;
        }
        if (RELU)
#pragma unroll
            for (int p = 0; p < 8; p++) o[p] = fmaxf(o[p], 0.f);
        float* dst = Y + (((size_t)b * 64 + oc) * 128 + y) * 128 + p0;
        *(float4*)dst = make_float4(o[0], o[1], o[2], o[3]);
        *(float4*)(dst + 4) = make_float4(o[4], o[5], o[6], o[7]);
    }
}

// ---- LayerNorm(HID=64) + keys/vals projection: 128pos x 128j per block ----
__global__ __launch_bounds__(256) void lnkv_kernel(
    const float* __restrict__ gv, const float* __restrict__ bv,
    const float* __restrict__ kb, const float* __restrict__ vb) {
    __shared__ __align__(16) float Xs[64 * 128];
    const int b = blockIdx.y, pbase = blockIdx.x * 128, tid = threadIdx.x;
    const float* eb = g_bufA + (size_t)b * 64 * NPOS + pbase;
    for (int i = tid; i < 64 * 128; i += 256) {
        int c = i >> 7, p = i & 127;
        Xs[c * 128 + p] = eb[(size_t)c * NPOS + p];
    }
    __syncthreads();
    if (tid < 128) {
        const int p = tid;
        float s = 0.f, s2 = 0.f;
#pragma unroll 8
        for (int c = 0; c < 64; c++) {
            float x = Xs[c * 128 + p];
            s += x;
            s2 += x * x;
        }
        float m = s * (1.f / 64.f);
        float var = s2 * (1.f / 64.f) - m * m;
        float rs = rsqrtf(var + 1e-5f);
#pragma unroll 8
        for (int c = 0; c < 64; c++)
            Xs[c * 128 + p] = (Xs[c * 128 + p] - m) * rs * __ldg(&gv[c]) + __ldg(&bv[c]);
    }
    __syncthreads();
    const int j0 = (tid >> 4) * 8, p0 = (tid & 15) * 8;
    unsigned long long acc[8][4];
#pragma unroll
    for (int i = 0; i < 8; i++)
#pragma unroll
        for (int j = 0; j < 4; j++) acc[i][j] = 0ull;
#pragma unroll 4
    for (int c = 0; c < 64; c++) {
        float4 w0 = __ldg((const float4*)&g_WkvT[c * 128 + j0]);
        float4 w1 = __ldg((const float4*)&g_WkvT[c * 128 + j0 + 4]);
        ulonglong2 bA = *(const ulonglong2*)&Xs[c * 128 + p0];
        ulonglong2 bB = *(const ulonglong2*)&Xs[c * 128 + p0 + 4];
        unsigned long long bb[4] = {bA.x, bA.y, bB.x, bB.y};
        float wv[8] = {w0.x, w0.y, w0.z, w0.w, w1.x, w1.y, w1.z, w1.w};
#pragma unroll
        for (int i = 0; i < 8; i++) {
            unsigned long long a = dup2(wv[i]);
#pragma unroll
            for (int j = 0; j < 4; j++) fma2(acc[i][j], a, bb[j]);
        }
    }
    const bool isK = (j0 < 64);
    float* outp = isK ? g_keys : g_vals;
    const int jj0 = isK ? j0 : (j0 - 64);
    const float* bp = isK ? kb : vb;
    float b8[8];
#pragma unroll
    for (int i = 0; i < 8; i++) b8[i] = bp[jj0 + i];
#pragma unroll
    for (int pp = 0; pp < 8; pp++) {
        float o[8];
#pragma unroll
        for (int i = 0; i < 8; i++) {
            float2 v = unpk(acc[i][pp >> 1]);
            o[i] = ((pp & 1) ? v.y : v.x) + b8[i];
        }
        float* dst = outp + ((size_t)b * NPOS + pbase + p0 + pp) * 64 + jj0;
        *(float4*)dst = make_float4(o[0], o[1], o[2], o[3]);
        *(float4*)(dst + 4) = make_float4(o[4], o[5], o[6], o[7]);
    }
}

// ---- vals column-sum ----
__global__ void vsum_kernel() {
    int b = blockIdx.x, tid = threadIdx.x, qd = tid & 63, grp = tid >> 6;
    float s = 0.f;
    for (int n = grp; n < NPOS; n += 4) s += g_vals[((size_t)b * NPOS + n) * 64 + qd];
    __shared__ float sm[256];
    sm[tid] = s;
    __syncthreads();
    if (tid < 64) g_vsum[b * 64 + tid] = sm[tid] + sm[tid + 64] + sm[tid + 128] + sm[tid + 192];
}

__global__ void copy_kernel(const float* __restrict__ src, int n) {
    int i = blockIdx.x * blockDim.x + threadIdx.x;
    if (i < n) g_qbuf[i] = src[i];
}

__global__ void diag_kernel(float* __restrict__ out, int n, float code) {
    int i = blockIdx.x * blockDim.x + threadIdx.x;
    if (i < n) out[i] = code;
}

// ---- slot LayerNorm, pre-scaled by 10/sqrt(Q)=1.25 ----
__global__ void qnorm_kernel(const float* __restrict__ g, const float* __restrict__ bb) {
    int row = blockIdx.x, d = threadIdx.x;
    float x = g_qbuf[row * 64 + d];
    float su = x, sq = x * x;
    for (int off = 16; off; off >>= 1) {
        su += __shfl_xor_sync(0xffffffffu, su, off);
        sq += __shfl_xor_sync(0xffffffffu, sq, off);
    }
    __shared__ float s0[2], s1[2];
    if ((d & 31) == 0) {
        s0[d >> 5] = su;
        s1[d >> 5] = sq;
    }
    __syncthreads();
    float ts = s0[0] + s0[1], tq = s1[0] + s1[1];
    float m = ts * (1.f / 64.f);
    float v = tq * (1.f / 64.f) - m * m;
    g_qn[row * 64 + d] = ((x - m) * rsqrtf(v + 1e-5f) * g[d] + bb[d]) * 1.25f;
}

// ---- attention: logits + softmax over slots + partial num/den ----
__global__ __launch_bounds__(256) void attn_kernel() {
    const int b = blockIdx.y, ch = blockIdx.x, tid = threadIdx.x;
    const int w = tid >> 5, l = tid & 31;
    __shared__ __align__(16) float qs[NSLOT * 64];
    for (int i = tid; i < NSLOT * 64; i += 256) qs[i] = g_qn[b * NSLOT * 64 + i];
    __syncthreads();
    float n0[NSLOT], n1[NSLOT], den[NSLOT];
#pragma unroll
    for (int s = 0; s < NSLOT; s++) n0[s] = n1[s] = den[s] = 0.f;
    const int nbase = ch * 1024 + w * 128;
    const float2* kp = (const float2*)(g_keys + ((size_t)b * NPOS + nbase) * 64) + l;
    const float2* vp = (const float2*)(g_vals + ((size_t)b * NPOS + nbase) * 64) + l;
    float2 qq[NSLOT];
#pragma unroll
    for (int s = 0; s < NSLOT; s++) qq[s] = *(const float2*)&qs[s * 64 + 2 * l];
    for (int i = 0; i < 128; i++) {
        float2 kk = kp[i * 32], vv = vp[i * 32];
        float lg[NSLOT];
#pragma unroll
        for (int s = 0; s < NSLOT; s++) {
            float p = kk.x * qq[s].x + kk.y * qq[s].y;
            p += __shfl_xor_sync(0xffffffffu, p, 16);
            p += __shfl_xor_sync(0xffffffffu, p, 8);
            p += __shfl_xor_sync(0xffffffffu, p, 4);
            p += __shfl_xor_sync(0xffffffffu, p, 2);
            p += __shfl_xor_sync(0xffffffffu, p, 1);
            lg[s] = p;
        }
        float mx = lg[0];
#pragma unroll
        for (int s = 1; s < NSLOT; s++) mx = fmaxf(mx, lg[s]);
        float e[NSLOT], sum = 0.f;
#pragma unroll
        for (int s = 0; s < NSLOT; s++) {
            e[s] = __expf(lg[s] - mx);
            sum += e[s];
        }
        float inv = 1.f / sum;
#pragma unroll
        for (int s = 0; s < NSLOT; s++) {
            float a = e[s] * inv;
            den[s] += a;
            n0[s] += a * vv.x;
            n1[s] += a * vv.y;
        }
    }
    size_t base = (size_t)b * 128 + ch * 8 + w;
    float* np = g_numP + base * (NSLOT * 64);
#pragma unroll
    for (int s = 0; s < NSLOT; s++)
        *(float2*)&np[s * 64 + 2 * l] = make_float2(n0[s], n1[s]);
    if (l == 0)
#pragma unroll
        for (int s = 0; s < NSLOT; s++) g_denP[base * NSLOT + s] = den[s];
}

// ---- reduce partials -> upd ----
__global__ void reduce_upd_kernel() {
    const int b = blockIdx.x, tid = threadIdx.x;  // 448 threads
    const int s = tid / 64, d = tid % 64;
    float den = 0.f, num = 0.f;
    for (int i = 0; i < 128; i++) {
        den += g_denP[((size_t)b * 128 + i) * NSLOT + s];
        num += g_numP[((size_t)b * 128 + i) * (NSLOT * 64) + tid];
    }
    g_upd[b * 448 + tid] = num / den + 1e-8f * g_vsum[b * 64 + d];
}

// ---- GRU + LN + FF (q in place) ----
__device__ __forceinline__ float sigm(float x) { return 1.f / (1.f + __expf(-x)); }
__global__ __launch_bounds__(256) void gru_ff_kernel(
    const float* __restrict__ bih, const float* __restrict__ bhh,
    const float* __restrict__ ug, const float* __restrict__ ub,
    const float* __restrict__ f1w, const float* __restrict__ f1b,
    const float* __restrict__ f2w, const float* __restrict__ f2b) {
    __shared__ float ups[448], hs[448], hns[448], lnh[448];
    __shared__ float gis[1344], ghs[1344], f1s[112], mv[14];
    const int b = blockIdx.x, tid = threadIdx.x;
    for (int i = tid; i < 448; i += 256) {
        ups[i] = g_upd[b * 448 + i];
        hs[i] = g_qbuf[b * 448 + i];
    }
    __syncthreads();
    for (int idx = tid; idx < 2688; idx += 256) {
        int which = idx >= 1344, rem = idx - which * 1344;
        int s = rem / 192, j = rem % 192;
        const float* src = which ? &hs[s * 64] : &ups[s * 64];
        const float* wt = g_WgruT + which * 12288;
        float acc = which ? bhh[j] : bih[j];
#pragma unroll 16
        for (int c = 0; c < 64; c++) acc += src[c] * __ldg(&wt[c * 192 + j]);
        (which ? ghs : gis)[rem] = acc;
    }
    __syncthreads();
    for (int idx = tid; idx < 448; idx += 256) {
        int s = idx / 64, d = idx % 64;
        float r = sigm(gis[s * 192 + d] + ghs[s * 192 + d]);
        float z = sigm(gis[s * 192 + 64 + d] + ghs[s * 192 + 64 + d]);
        float nn = tanhf(gis[s * 192 + 128 + d] + r * ghs[s * 192 + 128 + d]);
        hns[idx] = (1.f - z) * nn + z * hs[idx];
    }
    __syncthreads();
    if (tid < 224) {
        int s = tid >> 5, l = tid & 31;
        float x0 = hns[s * 64 + l], x1 = hns[s * 64 + 32 + l];
        float su = x0 + x1, sq = x0 * x0 + x1 * x1;
        for (int off = 16; off; off >>= 1) {
            su += __shfl_xor_sync(0xffffffffu, su, off);
            sq += __shfl_xor_sync(0xffffffffu, sq, off);
        }
        if (l == 0) {
            float m = su * (1.f / 64.f);
            float v = sq * (1.f / 64.f) - m * m;
            mv[s * 2] = m;
            mv[s * 2 + 1] = rsqrtf(v + 1e-5f);
        }
    }
    __syncthreads();
    for (int idx = tid; idx < 448; idx += 256) {
        int s = idx / 64, d = idx % 64;
        lnh[idx] = (hns[idx] - mv[s * 2]) * mv[s * 2 + 1] * ug[d] + ub[d];
    }
    __syncthreads();
    for (int idx = tid; idx < 112; idx += 256) {
        int s = idx / 16, k = idx % 16;
        float acc = f1b[k];
#pragma unroll 16
        for (int d = 0; d < 64; d++) acc += lnh[s * 64 + d] * f1w[k * 64 + d];
        f1s[idx] = fmaxf(acc, 0.f);
    }
    __syncthreads();
    for (int idx = tid; idx < 448; idx += 256) {
        int s = idx / 64, d = idx % 64;
        float acc = f2b[d];
#pragma unroll
        for (int k = 0; k < 16; k++) acc += f1s[s * 16 + k] * f2w[d * 16 + k];
        g_qbuf[b * 448 + idx] = hns[idx] + acc;
    }
}

// ---- final projection + output ----
__global__ void final_kernel(const float* __restrict__ fw, const float* __restrict__ fb,
                             float* __restrict__ out, int out_size) {
    const int b = blockIdx.x, tid = threadIdx.x;  // 512 threads
    if (tid < 448) {
        int oi = BATCH * NSLOT * 2 + b * 448 + tid;
        if (oi < out_size) out[oi] = g_qbuf[b * 448 + tid];
    } else if (tid < 448 + NSLOT * 2) {
        int idx = tid - 448, s = idx >> 1, o = idx & 1;
        float acc = fb[o];
#pragma unroll 16
        for (int d = 0; d < 64; d++) acc += g_qbuf[b * 448 + s * 64 + d] * fw[o * 64 + d];
        int oi = (b * NSLOT + s) * 2 + o;
        if (oi < out_size) out[oi] = acc;
    }
}

// Element counts (HID=64), reference-signature (insertion) order.
static const int SZ_INS[28] = {2621440, 14336, 8000, 64, 102400, 64, 102400, 64,
                               64, 64, 64, 64, 64, 64, 4096, 64, 4096, 64,
                               12288, 12288, 192, 192, 1024, 16, 1024, 64, 128, 2};
static const int SZ_ALPHA[28] = {64, 8000, 64, 102400, 64, 102400, 2621440, 64,
                                 64, 16, 1024, 64, 1024, 2, 128, 192, 192, 12288,
                                 12288, 64, 64, 14336, 64, 4096, 64, 4096, 64, 64};
static const int MAP_ALPHA[28] = {6, 21, 1, 0, 3, 2, 5, 4, 8, 7, 20, 19, 27, 26,
                                  23, 22, 25, 24, 18, 17, 16, 15, 10, 9, 12, 11, 14, 13};

extern "C" void kernel_launch(void* const* d_in, const int* in_sizes, int n_in,
                              void* d_out, int out_size) {
    float* out = (float*)d_out;
    const float* in[28];
    bool resolved = false;

    if (n_in >= 28) {
        for (int s = 1; s <= 4 && !resolved; s *= 4) {
            bool ins = true, alpha = true;
            for (int i = 0; i < 28; i++) {
                if (in_sizes[i] != SZ_INS[i] * s) ins = false;
                if (in_sizes[i] != SZ_ALPHA[i] * s) alpha = false;
            }
            if (ins) {
                for (int i = 0; i < 28; i++) in[i] = (const float*)d_in[i];
                resolved = true;
            } else if (alpha) {
                for (int i = 0; i < 28; i++) in[i] = (const float*)d_in[MAP_ALPHA[i]];
                resolved = true;
            }
        }
        for (int s = 1; s <= 4 && !resolved; s *= 4) {
            bool used[64];
            for (int k = 0; k < 64; k++) used[k] = false;
            bool okk = true;
            for (int i = 0; i < 28 && okk; i++) {
                int j = -1;
                for (int k = 0; k < n_in && k < 64; k++)
                    if (!used[k] && in_sizes[k] == SZ_INS[i] * s) { j = k; break; }
                if (j < 0) okk = false;
                else { used[j] = true; in[i] = (const float*)d_in[j]; }
            }
            if (okk) resolved = true;
        }
    }
    if (!resolved) {
        float code = (float)((double)n_in * 1e6 + (double)(n_in > 0 ? (in_sizes[0] % 1000000) : 0));
        diag_kernel<<<(out_size + 255) / 256, 256>>>(out, out_size, code);
        return;
    }

    const float* data = in[0];
    const float* slots = in[1];
    const float* c1b = in[3];
    const float* c2b = in[5];
    const float* c3b = in[7];
    const float* dng = in[8];
    const float* dnb = in[9];
    const float* qng = in[10];
    const float* qnb = in[11];
    const float* ung = in[12];
    const float* unb = in[13];
    const float* tkb = in[15];
    const float* tvb = in[17];
    const float* bih = in[20];
    const float* bhh = in[21];
    const float* f1w = in[22];
    const float* f1b = in[23];
    const float* f2w = in[24];
    const float* f2b = in[25];
    const float* fw = in[26];
    const float* fb = in[27];

    prep_weights<<<400, 256>>>(in[2], in[4], in[6], in[14], in[16], in[18], in[19]);
    conv5x5_kernel<5, true, 0, 1, 1><<<dim3(128, 32), 256>>>(data, c1b);
    conv5x5_kernel<64, true, 1, 2, 2><<<dim3(128, 32), 256>>>(nullptr, c2b);
    conv5x5_kernel<64, false, 2, 1, 3><<<dim3(128, 32), 256>>>(nullptr, c3b);
    lnkv_kernel<<<dim3(128, 32), 256>>>(dng, dnb, tkb, tvb);
    vsum_kernel<<<32, 256>>>();
    copy_kernel<<<56, 256>>>(slots, BATCH * NSLOT * QDIM);
    for (int it = 0; it < 3; it++) {
        qnorm_kernel<<<BATCH * NSLOT, 64>>>(qng, qnb);
        attn_kernel<<<dim3(16, BATCH), 256>>>();
        reduce_upd_kernel<<<BATCH, 448>>>();
        gru_ff_kernel<<<BATCH, 256>>>(bih, bhh, ung, unb, f1w, f1b, f2w, f2b);
    }
    final_kernel<<<BATCH, 512>>>(fw, fb, out, out_size);
}